// round 9
// baseline (speedup 1.0000x reference)
#include <cuda_runtime.h>
#include <cuda_fp16.h>
#include <cstdint>

#define NB 16
#define NC 128
#define NN 4096
#define NGROUPS 8
#define CPG 16
#define LOG2E 1.4426950408889634f
#define QSCALE 0.12751709943503907f   // (1/sqrt(128))*log2(e)

__device__ float  g_mean[NB * NGROUPS];
__device__ float  g_rstd[NB * NGROUPS];
__device__ __half g_q[(size_t)NB * NC * NN];   // f16 q [b][n][c]
__device__ __half g_k[(size_t)NB * NC * NN];   // f16 k [b][n][c]
__device__ __half g_v[(size_t)NB * NC * NN];   // f16 v [b][c][n]
__device__ __half g_o[(size_t)NB * NC * NN];   // f16 o [b][c][n]
__device__ int8_t g_q8[(size_t)NB * NC * NN];  // int8 q [b][n][c]
__device__ int8_t g_k8[(size_t)NB * NC * NN];  // int8 k [b][n][c]
__device__ float  g_dq[(size_t)NB * NN];       // per-row dequant factors
__device__ float  g_dk[(size_t)NB * NN];

__device__ __forceinline__ uint32_t sptr(const void* p) { return (uint32_t)__cvta_generic_to_shared(p); }
__device__ __forceinline__ void ldm_x4(uint32_t* r, uint32_t a) {
    asm volatile("ldmatrix.sync.aligned.m8n8.x4.shared.b16 {%0,%1,%2,%3}, [%4];"
                 : "=r"(r[0]), "=r"(r[1]), "=r"(r[2]), "=r"(r[3]) : "r"(a));
}
__device__ __forceinline__ void ldm_x4_t(uint32_t* r, uint32_t a) {
    asm volatile("ldmatrix.sync.aligned.m8n8.x4.trans.shared.b16 {%0,%1,%2,%3}, [%4];"
                 : "=r"(r[0]), "=r"(r[1]), "=r"(r[2]), "=r"(r[3]) : "r"(a));
}
__device__ __forceinline__ void mma16816(float* c, const uint32_t* a, const uint32_t* b) {
    asm volatile("mma.sync.aligned.m16n8k16.row.col.f32.f16.f16.f32 "
                 "{%0,%1,%2,%3}, {%4,%5,%6,%7}, {%8,%9}, {%0,%1,%2,%3};"
                 : "+f"(c[0]), "+f"(c[1]), "+f"(c[2]), "+f"(c[3])
                 : "r"(a[0]), "r"(a[1]), "r"(a[2]), "r"(a[3]), "r"(b[0]), "r"(b[1]));
}
__device__ __forceinline__ void mma8(int* d, const uint32_t* a, uint32_t b0, uint32_t b1) {
    asm volatile("mma.sync.aligned.m16n8k32.row.col.s32.s8.s8.s32 "
                 "{%0,%1,%2,%3}, {%4,%5,%6,%7}, {%8,%9}, {%0,%1,%2,%3};"
                 : "+r"(d[0]), "+r"(d[1]), "+r"(d[2]), "+r"(d[3])
                 : "r"(a[0]), "r"(a[1]), "r"(a[2]), "r"(a[3]), "r"(b0), "r"(b1));
}
__device__ __forceinline__ float ex2f(float x) {
    float y; asm("ex2.approx.f32 %0, %1;" : "=f"(y) : "f"(x)); return y;
}
__device__ __forceinline__ uint32_t exp2pack(float lo, float hi) {
    uint32_t h, r;
    asm("cvt.rn.f16x2.f32 %0, %1, %2;" : "=r"(h) : "f"(hi), "f"(lo));
    asm("ex2.approx.f16x2 %0, %1;" : "=r"(r) : "r"(h));
    return r;
}
__device__ __forceinline__ uint32_t packh2(float a, float b) {
    __half2 h = __floats2half2_rn(a, b);
    return *reinterpret_cast<uint32_t*>(&h);
}
__device__ __forceinline__ void cpa16(void* dst, const void* src) {
    asm volatile("cp.async.cg.shared.global [%0], [%1], 16;\n" :: "r"(sptr(dst)), "l"(src));
}
#define CP_COMMIT() asm volatile("cp.async.commit_group;")

// ---------------- kernel 1: groupnorm stats ----------------
__global__ void gn_stats_kernel(const float* __restrict__ x) {
    int bg = blockIdx.x;
    const float* xp = x + (size_t)bg * (CPG * NN);
    float s = 0.f, ss = 0.f;
    for (int i = threadIdx.x * 4; i < CPG * NN; i += 256 * 4) {
        float4 v = *(const float4*)(xp + i);
        s  += (v.x + v.y) + (v.z + v.w);
        ss += v.x * v.x + v.y * v.y + v.z * v.z + v.w * v.w;
    }
#pragma unroll
    for (int o = 16; o; o >>= 1) {
        s  += __shfl_xor_sync(~0u, s, o);
        ss += __shfl_xor_sync(~0u, ss, o);
    }
    __shared__ float red[16];
    int warp = threadIdx.x >> 5;
    if ((threadIdx.x & 31) == 0) { red[warp] = s; red[8 + warp] = ss; }
    __syncthreads();
    if (threadIdx.x == 0) {
        float S = 0.f, SS = 0.f;
        for (int i = 0; i < 8; i++) { S += red[i]; SS += red[8 + i]; }
        float inv = 1.f / (float)(CPG * NN);
        float mean = S * inv;
        float var  = SS * inv - mean * mean;
        g_mean[bg] = mean;
        g_rstd[bg] = rsqrtf(var + 1e-5f);
    }
}

// ---------------- kernel 2: GN apply + QKV projection ----------------
// q (pre-scaled by QSCALE) and k written f16 transposed [n][c] via smem staging; v f16 [c][n].
#define QKV_SMEM (34816 * 2)

__global__ __launch_bounds__(256, 1) void qkv_kernel(
    const float* __restrict__ x, const float* __restrict__ gnw, const float* __restrict__ gnb,
    const float* __restrict__ wq, const float* __restrict__ bq,
    const float* __restrict__ wk, const float* __restrict__ bk,
    const float* __restrict__ wv, const float* __restrict__ bv)
{
    extern __shared__ char dynq[];
    __half (*xs)[136] = (__half(*)[136])dynq;            // [c][pos]
    __half (*ts)[136] = (__half(*)[136])(dynq + 34816);  // [pos][c] staging for q/k
    int b = blockIdx.y, p0 = blockIdx.x * 128;
    int tid = threadIdx.x;
    const float* xb = x + (size_t)b * NC * NN;

    for (int idx = tid; idx < 128 * 32; idx += 256) {
        int c = idx >> 5, u = idx & 31;
        float4 v = *(const float4*)(xb + (size_t)c * NN + p0 + u * 4);
        float ga = gnw[c] * g_rstd[b * NGROUPS + (c >> 4)];
        float be = gnb[c] - g_mean[b * NGROUPS + (c >> 4)] * ga;
        __half2* d = (__half2*)&xs[c][u * 4];
        d[0] = __floats2half2_rn(v.x * ga + be, v.y * ga + be);
        d[1] = __floats2half2_rn(v.z * ga + be, v.w * ga + be);
    }
    __syncthreads();

    int warp = tid >> 5, lane = tid & 31;
    int oc0 = warp * 16;
    int rr = lane >> 2, c2 = (lane & 3) * 2;
    int browoff = (lane & 7) + 8 * ((lane >> 3) & 1);
    int bcol = 8 * (lane >> 4);

    const float* Ws[3] = {wq, wk, wv};
    const float* Bi[3] = {bq, bk, bv};

    for (int m = 0; m < 3; m++) {
        const float* W = Ws[m];
        uint32_t A[8][4];
#pragma unroll
        for (int kb = 0; kb < 8; kb++) {
            int cc = kb * 16 + c2;
            float2 x0 = *(const float2*)(W + (size_t)(oc0 + rr) * NC + cc);
            float2 x1 = *(const float2*)(W + (size_t)(oc0 + rr + 8) * NC + cc);
            float2 x2 = *(const float2*)(W + (size_t)(oc0 + rr) * NC + cc + 8);
            float2 x3 = *(const float2*)(W + (size_t)(oc0 + rr + 8) * NC + cc + 8);
            A[kb][0] = packh2(x0.x, x0.y); A[kb][1] = packh2(x1.x, x1.y);
            A[kb][2] = packh2(x2.x, x2.y); A[kb][3] = packh2(x3.x, x3.y);
        }
        float br  = Bi[m][oc0 + rr];
        float br8 = Bi[m][oc0 + rr + 8];
        float pre = (m == 0) ? QSCALE : 1.f;
#pragma unroll
        for (int pp = 0; pp < 8; pp++) {
            float acc[8] = {0.f, 0.f, 0.f, 0.f, 0.f, 0.f, 0.f, 0.f};
#pragma unroll
            for (int kb = 0; kb < 8; kb++) {
                uint32_t bfr[4];
                ldm_x4_t(bfr, sptr(&xs[kb * 16 + browoff][pp * 16 + bcol]));
                mma16816(acc,     A[kb], bfr);
                mma16816(acc + 4, A[kb], bfr + 2);
            }
            int pc = pp * 16 + c2;   // tile-local position
            if (m < 2) {
                int oc = oc0 + rr, oc8 = oc + 8;
                ts[pc    ][oc]  = __float2half((acc[0] + br)  * pre);
                ts[pc + 1][oc]  = __float2half((acc[1] + br)  * pre);
                ts[pc    ][oc8] = __float2half((acc[2] + br8) * pre);
                ts[pc + 1][oc8] = __float2half((acc[3] + br8) * pre);
                ts[pc + 8][oc]  = __float2half((acc[4] + br)  * pre);
                ts[pc + 9][oc]  = __float2half((acc[5] + br)  * pre);
                ts[pc + 8][oc8] = __float2half((acc[6] + br8) * pre);
                ts[pc + 9][oc8] = __float2half((acc[7] + br8) * pre);
            } else {
                __half* out = g_v + (size_t)b * NC * NN;
                int pg = p0 + pc;
                *(__half2*)(out + (size_t)(oc0 + rr) * NN + pg)         = __floats2half2_rn(acc[0] + br,  acc[1] + br);
                *(__half2*)(out + (size_t)(oc0 + rr + 8) * NN + pg)     = __floats2half2_rn(acc[2] + br8, acc[3] + br8);
                *(__half2*)(out + (size_t)(oc0 + rr) * NN + pg + 8)     = __floats2half2_rn(acc[4] + br,  acc[5] + br);
                *(__half2*)(out + (size_t)(oc0 + rr + 8) * NN + pg + 8) = __floats2half2_rn(acc[6] + br8, acc[7] + br8);
            }
        }
        if (m < 2) {
            __syncthreads();
            __half* gt = (m == 0 ? g_q : g_k) + (size_t)b * NN * NC;
            for (int idx = tid; idx < 128 * 16; idx += 256) {
                int r = idx >> 4, u = idx & 15;
                *(uint4*)(gt + (size_t)(p0 + r) * NC + u * 8) = *(uint4*)&ts[r][u * 8];
            }
            __syncthreads();
        }
    }
}

// ---------------- kernel 2b: per-row int8 quantization of q and k ----------------
__global__ __launch_bounds__(256, 1) void quant_kernel() {
    int wid = threadIdx.x >> 5, lane = threadIdx.x & 31;
    size_t row = (size_t)blockIdx.x * 8 + wid;     // 0 .. NB*NN-1
    const __half* src = (blockIdx.y ? g_k : g_q) + row * NC;
    int8_t* dst = (blockIdx.y ? g_k8 : g_q8) + row * NC;
    float* dsc  = (blockIdx.y ? g_dk : g_dq) + row;

    uint2 u = *(const uint2*)(src + lane * 4);
    __half2 h0 = *(__half2*)&u.x, h1 = *(__half2*)&u.y;
    float f0 = __low2float(h0), f1 = __high2float(h0);
    float f2 = __low2float(h1), f3 = __high2float(h1);
    float mx = fmaxf(fmaxf(fabsf(f0), fabsf(f1)), fmaxf(fabsf(f2), fabsf(f3)));
#pragma unroll
    for (int o = 16; o; o >>= 1) mx = fmaxf(mx, __shfl_xor_sync(~0u, mx, o));
    float s = (mx > 0.f) ? 127.f / mx : 0.f;
    char4 c;
    c.x = (char)__float2int_rn(f0 * s);
    c.y = (char)__float2int_rn(f1 * s);
    c.z = (char)__float2int_rn(f2 * s);
    c.w = (char)__float2int_rn(f3 * s);
    *(char4*)(dst + lane * 4) = c;
    if (lane == 0) *dsc = mx * (1.f / 127.f);
}

// ---------------- kernel 3: flash attention: int8 QK (m16n8k32) + per-row scales, f16 PV ----------------
// stage = K int8 [64 j][144] (9216B) + V f16 [128 c][72] (18432B) = 27648B; 3 stages + 16KB dk table.
#define STAGE_B 27648
#define ATTN_SMEM (3 * STAGE_B + 16384)

__global__ __launch_bounds__(256, 1) void attn_kernel() {
    extern __shared__ char dynb[];
    float* skf = (float*)(dynb + 3 * STAGE_B);   // dk[4096] for this batch

    int b = blockIdx.y, i0 = blockIdx.x * 128;
    int tid = threadIdx.x, warp = tid >> 5, lane = tid & 31;
    size_t off = (size_t)b * NC * NN;
    const int8_t* q8 = g_q8 + off;
    const int8_t* k8 = g_k8 + off;

    // ---- stage Q int8 tile [128 i][128 c] into stage-0 region (rows padded to 144) ----
    for (int idx = tid; idx < 1024; idx += 256) {
        int r = idx >> 3, u = idx & 7;
        *(uint4*)(dynb + r * 144 + u * 16) = *(const uint4*)(q8 + (size_t)(i0 + r) * NC + u * 16);
    }
    // dk table -> smem
    for (int idx = tid; idx < 1024; idx += 256)
        *(float4*)&skf[idx * 4] = *(const float4*)(g_dk + (size_t)b * NN + idx * 4);
    __syncthreads();
    uint32_t QA8[4][4];
    {
        int ar = warp * 16 + (lane & 7) + 8 * ((lane >> 3) & 1);
        int ac = 16 * (lane >> 4);
#pragma unroll
        for (int kb = 0; kb < 4; kb++)
            ldm_x4(QA8[kb], sptr(dynb + ar * 144 + kb * 32 + ac));
    }
    // per-row q dequant factors (fragment rows r, r+8)
    float dq0 = g_dq[(size_t)b * NN + i0 + warp * 16 + (lane >> 2)];
    float dq1 = g_dq[(size_t)b * NN + i0 + warp * 16 + (lane >> 2) + 8];
    __syncthreads();

    // ---- prologue: prefetch tiles 0,1,2 ----
#pragma unroll
    for (int s = 0; s < 3; s++) {
        char* ks = dynb + s * STAGE_B;
        char* vs = ks + 9216;
#pragma unroll
        for (int it = 0; it < 2; it++) {
            int i = tid + it * 256, r = i >> 3, u = i & 7;
            cpa16(ks + r * 144 + u * 16, k8 + (size_t)(s * 64 + r) * NC + u * 16);
        }
#pragma unroll
        for (int it = 0; it < 4; it++) {
            int i = tid + it * 256, c = i >> 3, u = i & 7;
            cpa16(vs + c * 144 + u * 16, g_v + off + (size_t)c * NN + s * 64 + u * 8);
        }
        CP_COMMIT();
    }

    float O[16][4];
#pragma unroll
    for (int i = 0; i < 16; i++) { O[i][0] = O[i][1] = O[i][2] = O[i][3] = 0.f; }
    float m0 = -1e30f, m1 = -1e30f, l0 = 0.f, l1 = 0.f;

    int brow = 8 * (lane >> 4) + (lane & 7);
    int bcolb = 16 * ((lane >> 3) & 1);
    int vrow = 8 * (lane >> 4) + (lane & 7);
    int vcol = 8 * ((lane >> 3) & 1);

    for (int jb = 0; jb < 64; jb++) {
        if (jb <= 61)      asm volatile("cp.async.wait_group 2;");
        else if (jb == 62) asm volatile("cp.async.wait_group 1;");
        else               asm volatile("cp.async.wait_group 0;");
        __syncthreads();

        char* ks = dynb + (jb % 3) * STAGE_B;
        __half (*Vs)[72] = (__half(*)[72])(ks + 9216);

        // S = Q K^T via int8 m16n8k32, dequant with per-row factors
        float S[8][4];
#pragma unroll
        for (int jp = 0; jp < 4; jp++) {
            int a0[4] = {0, 0, 0, 0}, a1[4] = {0, 0, 0, 0};
#pragma unroll
            for (int kb = 0; kb < 4; kb++) {
                uint32_t r[4];
                ldm_x4(r, sptr(ks + (jp * 16 + brow) * 144 + kb * 32 + bcolb));
                mma8(a0, QA8[kb], r[0], r[1]);
                mma8(a1, QA8[kb], r[2], r[3]);
            }
            int cb = jb * 64 + jp * 16 + (lane & 3) * 2;
            float2 sA = *(float2*)&skf[cb];
            float2 sB = *(float2*)&skf[cb + 8];
            S[2 * jp][0]     = (float)a0[0] * (dq0 * sA.x);
            S[2 * jp][1]     = (float)a0[1] * (dq0 * sA.y);
            S[2 * jp][2]     = (float)a0[2] * (dq1 * sA.x);
            S[2 * jp][3]     = (float)a0[3] * (dq1 * sA.y);
            S[2 * jp + 1][0] = (float)a1[0] * (dq0 * sB.x);
            S[2 * jp + 1][1] = (float)a1[1] * (dq0 * sB.y);
            S[2 * jp + 1][2] = (float)a1[2] * (dq1 * sB.x);
            S[2 * jp + 1][3] = (float)a1[3] * (dq1 * sB.y);
        }

        // row max
        float r0 = S[0][0], r1 = S[0][2];
#pragma unroll
        for (int t = 0; t < 8; t++) {
            r0 = fmaxf(r0, fmaxf(S[t][0], S[t][1]));
            r1 = fmaxf(r1, fmaxf(S[t][2], S[t][3]));
        }
        r0 = fmaxf(r0, __shfl_xor_sync(~0u, r0, 1)); r0 = fmaxf(r0, __shfl_xor_sync(~0u, r0, 2));
        r1 = fmaxf(r1, __shfl_xor_sync(~0u, r1, 1)); r1 = fmaxf(r1, __shfl_xor_sync(~0u, r1, 2));
        float nm0 = fmaxf(m0, r0), nm1 = fmaxf(m1, r1);
        float a0s = ex2f(m0 - nm0), a1s = ex2f(m1 - nm1);
        m0 = nm0; m1 = nm1;

        // P = exp2(S - m) packed f16 (PV A-fragments); sums via HADD2
        uint32_t PA[4][4];
        __half2 hs0 = __floats2half2_rn(0.f, 0.f), hs1 = hs0;
#pragma unroll
        for (int j = 0; j < 4; j++) {
            PA[j][0] = exp2pack(S[2*j][0]   - nm0, S[2*j][1]   - nm0);
            PA[j][1] = exp2pack(S[2*j][2]   - nm1, S[2*j][3]   - nm1);
            PA[j][2] = exp2pack(S[2*j+1][0] - nm0, S[2*j+1][1] - nm0);
            PA[j][3] = exp2pack(S[2*j+1][2] - nm1, S[2*j+1][3] - nm1);
            hs0 = __hadd2(hs0, __hadd2(*(__half2*)&PA[j][0], *(__half2*)&PA[j][2]));
            hs1 = __hadd2(hs1, __hadd2(*(__half2*)&PA[j][1], *(__half2*)&PA[j][3]));
        }
        float rs0 = __low2float(hs0) + __high2float(hs0);
        float rs1 = __low2float(hs1) + __high2float(hs1);
        rs0 += __shfl_xor_sync(~0u, rs0, 1); rs0 += __shfl_xor_sync(~0u, rs0, 2);
        rs1 += __shfl_xor_sync(~0u, rs1, 1); rs1 += __shfl_xor_sync(~0u, rs1, 2);
        l0 = l0 * a0s + rs0;
        l1 = l1 * a1s + rs1;
#pragma unroll
        for (int t = 0; t < 16; t++) { O[t][0] *= a0s; O[t][1] *= a0s; O[t][2] *= a1s; O[t][3] *= a1s; }

        // O += P V  (f16, f32 accum)
#pragma unroll
        for (int cp = 0; cp < 8; cp++) {
#pragma unroll
            for (int j = 0; j < 4; j++) {
                uint32_t bfr[4];
                ldm_x4(bfr, sptr((char*)&Vs[cp * 16 + vrow][vcol] + j * 32));
                mma16816(O[2 * cp],     PA[j], bfr);
                mma16816(O[2 * cp + 1], PA[j], bfr + 2);
            }
        }
        __syncthreads();

        // prefetch tile jb+3 into slot (jb+3)%3
        if (jb + 3 < 64) {
            char* ks2 = dynb + (jb % 3) * STAGE_B;
            char* vs2 = ks2 + 9216;
#pragma unroll
            for (int it = 0; it < 2; it++) {
                int i = tid + it * 256, r = i >> 3, u = i & 7;
                cpa16(ks2 + r * 144 + u * 16, k8 + (size_t)((jb + 3) * 64 + r) * NC + u * 16);
            }
#pragma unroll
            for (int it = 0; it < 4; it++) {
                int i = tid + it * 256, c = i >> 3, u = i & 7;
                cpa16(vs2 + c * 144 + u * 16, g_v + off + (size_t)c * NN + (jb + 3) * 64 + u * 8);
            }
        }
        CP_COMMIT();
    }

    float il0 = 1.f / l0, il1 = 1.f / l1;
    int row = i0 + warp * 16 + (lane >> 2);
    int c2 = (lane & 3) * 2;
#pragma unroll
    for (int t = 0; t < 16; t++) {
        int c = t * 8 + c2;
        g_o[off + (size_t)c * NN + row]           = __float2half(O[t][0] * il0);
        g_o[off + (size_t)(c + 1) * NN + row]     = __float2half(O[t][1] * il0);
        g_o[off + (size_t)c * NN + row + 8]       = __float2half(O[t][2] * il1);
        g_o[off + (size_t)(c + 1) * NN + row + 8] = __float2half(O[t][3] * il1);
    }
}

// ---------------- kernel 4: final projection + bias + residual ----------------
__global__ __launch_bounds__(256, 1) void proj_kernel(
    const float* __restrict__ x, const float* __restrict__ wf,
    const float* __restrict__ bf, float* __restrict__ out)
{
    __shared__ __half os[128][136];
    int b = blockIdx.y, p0 = blockIdx.x * 128;
    int tid = threadIdx.x;
    size_t off = (size_t)b * NC * NN;
    const __half* op = g_o + off + p0;
    for (int idx = tid; idx < 2048; idx += 256) {
        int c = idx >> 4, u = idx & 15;
        *(uint4*)&os[c][u * 8] = *(const uint4*)(op + (size_t)c * NN + u * 8);
    }
    __syncthreads();

    int warp = tid >> 5, lane = tid & 31;
    int oc0 = warp * 16, rr = lane >> 2, c2 = (lane & 3) * 2;
    int browoff = (lane & 7) + 8 * ((lane >> 3) & 1);
    int bcol = 8 * (lane >> 4);

    uint32_t A[8][4];
#pragma unroll
    for (int kb = 0; kb < 8; kb++) {
        int cc = kb * 16 + c2;
        float2 x0 = *(const float2*)(wf + (size_t)(oc0 + rr) * NC + cc);
        float2 x1 = *(const float2*)(wf + (size_t)(oc0 + rr + 8) * NC + cc);
        float2 x2 = *(const float2*)(wf + (size_t)(oc0 + rr) * NC + cc + 8);
        float2 x3 = *(const float2*)(wf + (size_t)(oc0 + rr + 8) * NC + cc + 8);
        A[kb][0] = packh2(x0.x, x0.y); A[kb][1] = packh2(x1.x, x1.y);
        A[kb][2] = packh2(x2.x, x2.y); A[kb][3] = packh2(x3.x, x3.y);
    }
    float br = bf[oc0 + rr], br8 = bf[oc0 + rr + 8];
    const float* xb = x + off;
    float* ob = out + off;

#pragma unroll
    for (int pp = 0; pp < 8; pp++) {
        float acc[8] = {0.f, 0.f, 0.f, 0.f, 0.f, 0.f, 0.f, 0.f};
#pragma unroll
        for (int kb = 0; kb < 8; kb++) {
            uint32_t bfr[4];
            ldm_x4_t(bfr, sptr(&os[kb * 16 + browoff][pp * 16 + bcol]));
            mma16816(acc,     A[kb], bfr);
            mma16816(acc + 4, A[kb], bfr + 2);
        }
        int pc = p0 + pp * 16 + c2;
        size_t i00 = (size_t)(oc0 + rr) * NN + pc;
        size_t i10 = (size_t)(oc0 + rr + 8) * NN + pc;
        float2 xv;
        xv = *(const float2*)(xb + i00);
        *(float2*)(ob + i00) = make_float2(acc[0] + br + xv.x, acc[1] + br + xv.y);
        xv = *(const float2*)(xb + i10);
        *(float2*)(ob + i10) = make_float2(acc[2] + br8 + xv.x, acc[3] + br8 + xv.y);
        xv = *(const float2*)(xb + i00 + 8);
        *(float2*)(ob + i00 + 8) = make_float2(acc[4] + br + xv.x, acc[5] + br + xv.y);
        xv = *(const float2*)(xb + i10 + 8);
        *(float2*)(ob + i10 + 8) = make_float2(acc[6] + br8 + xv.x, acc[7] + br8 + xv.y);
    }
}

// ---------------- launch ----------------
extern "C" void kernel_launch(void* const* d_in, const int* in_sizes, int n_in,
                              void* d_out, int out_size)
{
    (void)in_sizes; (void)n_in; (void)out_size;
    const float* x  = (const float*)d_in[0];
    const float* gw = (const float*)d_in[1];
    const float* gb = (const float*)d_in[2];
    const float* wq = (const float*)d_in[3];
    const float* bq = (const float*)d_in[4];
    const float* wk = (const float*)d_in[5];
    const float* bk = (const float*)d_in[6];
    const float* wv = (const float*)d_in[7];
    const float* bv = (const float*)d_in[8];
    const float* wf = (const float*)d_in[9];
    const float* bf = (const float*)d_in[10];
    float* out = (float*)d_out;

    cudaFuncSetAttribute(qkv_kernel,  cudaFuncAttributeMaxDynamicSharedMemorySize, QKV_SMEM);
    cudaFuncSetAttribute(attn_kernel, cudaFuncAttributeMaxDynamicSharedMemorySize, ATTN_SMEM);

    gn_stats_kernel<<<NB * NGROUPS, 256>>>(x);
    qkv_kernel<<<dim3(32, NB), 256, QKV_SMEM>>>(x, gw, gb, wq, bq, wk, bk, wv, bv);
    quant_kernel<<<dim3(NB * NN / 8, 2), 256>>>();
    attn_kernel<<<dim3(32, NB), 256, ATTN_SMEM>>>();
    proj_kernel<<<dim3(32, NB), 256>>>(x, wf, bf, out);
}

// round 10
// speedup vs baseline: 1.5386x; 1.5386x over previous
#include <cuda_runtime.h>
#include <cuda_fp16.h>
#include <cstdint>

#define NB 16
#define NC 128
#define NN 4096
#define NGROUPS 8
#define CPG 16
#define LOG2E 1.4426950408889634f

// ---------------- scratch ----------------
__device__ float  g_mean[NB * NGROUPS];
__device__ float  g_rstd[NB * NGROUPS];
__device__ __half g_q[(size_t)NB * NC * NN];
__device__ __half g_k[(size_t)NB * NC * NN];
__device__ __half g_v[(size_t)NB * NC * NN];
__device__ __half g_o[(size_t)NB * NC * NN];

// ---------------- helpers ----------------
__device__ __forceinline__ uint32_t sptr(const void* p) {
    return (uint32_t)__cvta_generic_to_shared(p);
}
__device__ __forceinline__ void ldm_x4(uint32_t* r, uint32_t a) {
    asm volatile("ldmatrix.sync.aligned.m8n8.x4.shared.b16 {%0,%1,%2,%3}, [%4];"
                 : "=r"(r[0]), "=r"(r[1]), "=r"(r[2]), "=r"(r[3]) : "r"(a));
}
__device__ __forceinline__ void ldm_x4_t(uint32_t* r, uint32_t a) {
    asm volatile("ldmatrix.sync.aligned.m8n8.x4.trans.shared.b16 {%0,%1,%2,%3}, [%4];"
                 : "=r"(r[0]), "=r"(r[1]), "=r"(r[2]), "=r"(r[3]) : "r"(a));
}
__device__ __forceinline__ void mma16816(float* c, const uint32_t* a, const uint32_t* b) {
    asm volatile("mma.sync.aligned.m16n8k16.row.col.f32.f16.f16.f32 "
                 "{%0,%1,%2,%3}, {%4,%5,%6,%7}, {%8,%9}, {%0,%1,%2,%3};"
                 : "+f"(c[0]), "+f"(c[1]), "+f"(c[2]), "+f"(c[3])
                 : "r"(a[0]), "r"(a[1]), "r"(a[2]), "r"(a[3]), "r"(b[0]), "r"(b[1]));
}
__device__ __forceinline__ float ex2f(float x) {
    float y; asm("ex2.approx.f32 %0, %1;" : "=f"(y) : "f"(x)); return y;
}
__device__ __forceinline__ uint32_t exp2pack(float lo, float hi) {
    uint32_t h, r;
    asm("cvt.rn.f16x2.f32 %0, %1, %2;" : "=r"(h) : "f"(hi), "f"(lo));
    asm("ex2.approx.f16x2 %0, %1;" : "=r"(r) : "r"(h));
    return r;
}
__device__ __forceinline__ uint32_t packh2(float a, float b) {
    __half2 h = __floats2half2_rn(a, b);
    return *reinterpret_cast<uint32_t*>(&h);
}
__device__ __forceinline__ void cpa16(void* dst, const void* src) {
    asm volatile("cp.async.cg.shared.global [%0], [%1], 16;\n"
                 :: "r"(sptr(dst)), "l"(src));
}
#define CP_COMMIT() asm volatile("cp.async.commit_group;")

// ---------------- kernel 1: groupnorm stats ----------------
__global__ void gn_stats_kernel(const float* __restrict__ x) {
    int bg = blockIdx.x;
    const float* xp = x + (size_t)bg * (CPG * NN);
    float s = 0.f, ss = 0.f;
    for (int i = threadIdx.x * 4; i < CPG * NN; i += 256 * 4) {
        float4 v = *(const float4*)(xp + i);
        s  += (v.x + v.y) + (v.z + v.w);
        ss += v.x * v.x + v.y * v.y + v.z * v.z + v.w * v.w;
    }
#pragma unroll
    for (int o = 16; o; o >>= 1) {
        s  += __shfl_xor_sync(~0u, s, o);
        ss += __shfl_xor_sync(~0u, ss, o);
    }
    __shared__ float red[16];
    int warp = threadIdx.x >> 5;
    if ((threadIdx.x & 31) == 0) { red[warp] = s; red[8 + warp] = ss; }
    __syncthreads();
    if (threadIdx.x == 0) {
        float S = 0.f, SS = 0.f;
        for (int i = 0; i < 8; i++) { S += red[i]; SS += red[8 + i]; }
        float inv = 1.f / (float)(CPG * NN);
        float mean = S * inv;
        float var  = SS * inv - mean * mean;
        g_mean[bg] = mean;
        g_rstd[bg] = rsqrtf(var + 1e-5f);
    }
}

// ---------------- kernel 2: GN apply + QKV projection (fp16 mma) ----------------
__global__ __launch_bounds__(256, 1) void qkv_kernel(
    const float* __restrict__ x, const float* __restrict__ gnw, const float* __restrict__ gnb,
    const float* __restrict__ wq, const float* __restrict__ bq,
    const float* __restrict__ wk, const float* __restrict__ bk,
    const float* __restrict__ wv, const float* __restrict__ bv)
{
    __shared__ __half xs[128][136];
    int b = blockIdx.y, p0 = blockIdx.x * 128;
    int tid = threadIdx.x;
    const float* xb = x + (size_t)b * NC * NN;

    for (int idx = tid; idx < 128 * 32; idx += 256) {
        int c = idx >> 5, u = idx & 31;
        float4 v = *(const float4*)(xb + (size_t)c * NN + p0 + u * 4);
        float rstd = g_rstd[b * NGROUPS + (c >> 4)];
        float mean = g_mean[b * NGROUPS + (c >> 4)];
        float ga = gnw[c] * rstd;
        float be = gnb[c] - mean * ga;
        __half2* d = (__half2*)&xs[c][u * 4];
        d[0] = __floats2half2_rn(v.x * ga + be, v.y * ga + be);
        d[1] = __floats2half2_rn(v.z * ga + be, v.w * ga + be);
    }
    __syncthreads();

    int warp = tid >> 5, lane = tid & 31;
    int oc0 = warp * 16;
    int rr = lane >> 2, c2 = (lane & 3) * 2;
    int browoff = (lane & 7) + 8 * ((lane >> 3) & 1);
    int bcol = 8 * (lane >> 4);

    const float* Ws[3] = {wq, wk, wv};
    const float* Bi[3] = {bq, bk, bv};
    __half* Out[3] = {g_q + (size_t)b * NC * NN, g_k + (size_t)b * NC * NN, g_v + (size_t)b * NC * NN};
    const float qscale = 0.08838834764831845f * LOG2E;

    for (int m = 0; m < 3; m++) {
        const float* W = Ws[m];
        uint32_t A[8][4];
#pragma unroll
        for (int kb = 0; kb < 8; kb++) {
            int cc = kb * 16 + c2;
            float2 x0 = *(const float2*)(W + (size_t)(oc0 + rr) * NC + cc);
            float2 x1 = *(const float2*)(W + (size_t)(oc0 + rr + 8) * NC + cc);
            float2 x2 = *(const float2*)(W + (size_t)(oc0 + rr) * NC + cc + 8);
            float2 x3 = *(const float2*)(W + (size_t)(oc0 + rr + 8) * NC + cc + 8);
            A[kb][0] = packh2(x0.x, x0.y); A[kb][1] = packh2(x1.x, x1.y);
            A[kb][2] = packh2(x2.x, x2.y); A[kb][3] = packh2(x3.x, x3.y);
        }
        float br  = Bi[m][oc0 + rr];
        float br8 = Bi[m][oc0 + rr + 8];
        float sc = (m == 0) ? qscale : 1.f;
        __half* out = Out[m];
#pragma unroll
        for (int pp = 0; pp < 8; pp++) {
            float acc[8] = {0.f, 0.f, 0.f, 0.f, 0.f, 0.f, 0.f, 0.f};
#pragma unroll
            for (int kb = 0; kb < 8; kb++) {
                uint32_t bfr[4];
                ldm_x4_t(bfr, sptr(&xs[kb * 16 + browoff][pp * 16 + bcol]));
                mma16816(acc,     A[kb], bfr);
                mma16816(acc + 4, A[kb], bfr + 2);
            }
            int pc = p0 + pp * 16 + c2;
            *(__half2*)(out + (size_t)(oc0 + rr) * NN + pc)         = __floats2half2_rn((acc[0] + br) * sc, (acc[1] + br) * sc);
            *(__half2*)(out + (size_t)(oc0 + rr + 8) * NN + pc)     = __floats2half2_rn((acc[2] + br8) * sc, (acc[3] + br8) * sc);
            *(__half2*)(out + (size_t)(oc0 + rr) * NN + pc + 8)     = __floats2half2_rn((acc[4] + br) * sc, (acc[5] + br) * sc);
            *(__half2*)(out + (size_t)(oc0 + rr + 8) * NN + pc + 8) = __floats2half2_rn((acc[6] + br8) * sc, (acc[7] + br8) * sc);
        }
    }
}

// ---------------- kernel 3: flash attention, ping-pong PV one tile back ----------------
#define STAGE_H (2 * 128 * 72)               // halves per stage (K + V tile)
#define ATTN_SMEM (3 * STAGE_H * 2)          // 110592 bytes

__global__ __launch_bounds__(256, 1) void attn_kernel() {
    extern __shared__ __half dyn[];

    int b = blockIdx.y, i0 = blockIdx.x * 128;
    int tid = threadIdx.x, warp = tid >> 5, lane = tid & 31;
    size_t off = (size_t)b * NC * NN;

    // ---- stage Q tile; build A-frags ----
    {
        __half (*Qs)[136] = (__half(*)[136])dyn;
        const __half* qp = g_q + off + i0;
        for (int idx = tid; idx < 2048; idx += 256) {
            int d = idx >> 4, u = idx & 15;
            *(uint4*)&Qs[d][u * 8] = *(const uint4*)(qp + (size_t)d * NN + u * 8);
        }
    }
    __syncthreads();
    uint32_t QA[8][4];
    {
        __half (*Qs)[136] = (__half(*)[136])dyn;
        int r  = 8 * (lane >> 4) + (lane & 7);
        int cq = warp * 16 + 8 * ((lane >> 3) & 1);
#pragma unroll
        for (int kb = 0; kb < 8; kb++)
            ldm_x4_t(QA[kb], sptr(&Qs[kb * 16 + r][cq]));
    }
    __syncthreads();

    // ---- prologue: prefetch tiles 0,1,2 into slots 0,1,2 ----
    {
        const __half* kb0 = g_k + off;
        const __half* vb0 = g_v + off;
#pragma unroll
        for (int s = 0; s < 3; s++) {
            __half* ks = dyn + s * STAGE_H;
            __half* vs = ks + 128 * 72;
            const __half* kp = kb0 + s * 64;
            const __half* vp = vb0 + s * 64;
#pragma unroll
            for (int it = 0; it < 4; it++) {
                int i = tid + it * 256;
                int c = i >> 3, u = i & 7;
                cpa16(ks + c * 72 + u * 8, kp + (size_t)c * NN + u * 8);
                cpa16(vs + c * 72 + u * 8, vp + (size_t)c * NN + u * 8);
            }
            CP_COMMIT();
        }
    }

    float O[16][4];
#pragma unroll
    for (int i = 0; i < 16; i++) { O[i][0] = O[i][1] = O[i][2] = O[i][3] = 0.f; }
    float m0 = -1e30f, m1 = -1e30f, l0 = 0.f, l1 = 0.f;
    uint32_t PA[4][4];   // P(t-1) fragments, persist across iterations

    int krow = (lane & 7) + 8 * ((lane >> 3) & 1);
    int kcol = 8 * (lane >> 4);
    int vrow = 8 * (lane >> 4) + (lane & 7);
    int vcol = 8 * ((lane >> 3) & 1);

    for (int jb = 0; jb < 64; jb++) {
        // wait schedule (commits: 3 prologue + one per iter 1..61)
        if (jb == 0)       asm volatile("cp.async.wait_group 2;");
        else if (jb <= 62) asm volatile("cp.async.wait_group 1;");
        else               asm volatile("cp.async.wait_group 0;");
        __syncthreads();

        __half (*Ks)[72] = (__half(*)[72])(dyn + (jb % 3) * STAGE_H);
        __half (*Vp)[72] = (__half(*)[72])(dyn + ((jb + 2) % 3) * STAGE_H + 128 * 72); // V(jb-1)

        // ---- QK(jb): S = Q K^T ----
        float S[8][4];
#pragma unroll
        for (int jp = 0; jp < 4; jp++) {
            float* s0 = S[2 * jp];
            float* s1 = S[2 * jp + 1];
            s0[0] = s0[1] = s0[2] = s0[3] = 0.f;
            s1[0] = s1[1] = s1[2] = s1[3] = 0.f;
#pragma unroll
            for (int kb = 0; kb < 8; kb++) {
                uint32_t bfr[4];
                ldm_x4_t(bfr, sptr(&Ks[kb * 16 + krow][jp * 16 + kcol]));
                mma16816(s0, QA[kb], bfr);
                mma16816(s1, QA[kb], bfr + 2);
            }
        }

        // ---- PV(jb-1): O += P(jb-1) V(jb-1) (independent of softmax below) ----
        if (jb > 0) {
#pragma unroll
            for (int cp = 0; cp < 8; cp++) {
#pragma unroll
                for (int j = 0; j < 4; j++) {
                    uint32_t bfr[4];
                    ldm_x4(bfr, sptr(&Vp[cp * 16 + vrow][j * 16 + vcol]));
                    mma16816(O[2 * cp],     PA[j], bfr);
                    mma16816(O[2 * cp + 1], PA[j], bfr + 2);
                }
            }
        }

        // ---- softmax(jb): overlaps with tensor-queue backlog ----
        float r0 = S[0][0], r1 = S[0][2];
#pragma unroll
        for (int t = 0; t < 8; t++) {
            r0 = fmaxf(r0, fmaxf(S[t][0], S[t][1]));
            r1 = fmaxf(r1, fmaxf(S[t][2], S[t][3]));
        }
        r0 = fmaxf(r0, __shfl_xor_sync(~0u, r0, 1)); r0 = fmaxf(r0, __shfl_xor_sync(~0u, r0, 2));
        r1 = fmaxf(r1, __shfl_xor_sync(~0u, r1, 1)); r1 = fmaxf(r1, __shfl_xor_sync(~0u, r1, 2));
        float nm0 = fmaxf(m0, r0), nm1 = fmaxf(m1, r1);
        float a0 = ex2f(m0 - nm0), a1 = ex2f(m1 - nm1);
        m0 = nm0; m1 = nm1;

        __half2 hs0 = __floats2half2_rn(0.f, 0.f), hs1 = hs0;
#pragma unroll
        for (int j = 0; j < 4; j++) {
            PA[j][0] = exp2pack(S[2*j][0]   - nm0, S[2*j][1]   - nm0);
            PA[j][1] = exp2pack(S[2*j][2]   - nm1, S[2*j][3]   - nm1);
            PA[j][2] = exp2pack(S[2*j+1][0] - nm0, S[2*j+1][1] - nm0);
            PA[j][3] = exp2pack(S[2*j+1][2] - nm1, S[2*j+1][3] - nm1);
            hs0 = __hadd2(hs0, __hadd2(*(__half2*)&PA[j][0], *(__half2*)&PA[j][2]));
            hs1 = __hadd2(hs1, __hadd2(*(__half2*)&PA[j][1], *(__half2*)&PA[j][3]));
        }
        float rs0 = __low2float(hs0) + __high2float(hs0);
        float rs1 = __low2float(hs1) + __high2float(hs1);
        rs0 += __shfl_xor_sync(~0u, rs0, 1); rs0 += __shfl_xor_sync(~0u, rs0, 2);
        rs1 += __shfl_xor_sync(~0u, rs1, 1); rs1 += __shfl_xor_sync(~0u, rs1, 2);
        l0 = l0 * a0 + rs0;
        l1 = l1 * a1 + rs1;

        // rescale O to scale m(jb)  (waits on PV(jb-1) completion)
#pragma unroll
        for (int t = 0; t < 16; t++) { O[t][0] *= a0; O[t][1] *= a0; O[t][2] *= a1; O[t][3] *= a1; }

        __syncthreads();   // all warps done reading V(jb-1) (slot (jb+2)%3) and K(jb)

        // refill slot (jb+2)%3 with tile jb+2 (V(jb-1) just consumed there)
        if (jb >= 1 && jb <= 61) {
            int sl = (jb + 2) % 3;
            __half* ks = dyn + sl * STAGE_H;
            __half* vs = ks + 128 * 72;
            const __half* kp = g_k + off + (jb + 2) * 64;
            const __half* vp = g_v + off + (jb + 2) * 64;
#pragma unroll
            for (int it = 0; it < 4; it++) {
                int i = tid + it * 256;
                int c = i >> 3, u = i & 7;
                cpa16(ks + c * 72 + u * 8, kp + (size_t)c * NN + u * 8);
                cpa16(vs + c * 72 + u * 8, vp + (size_t)c * NN + u * 8);
            }
            CP_COMMIT();
        }
    }

    // ---- drain: PV(63) ----
    {
        __half (*Vl)[72] = (__half(*)[72])(dyn + (63 % 3) * STAGE_H + 128 * 72);
#pragma unroll
        for (int cp = 0; cp < 8; cp++) {
#pragma unroll
            for (int j = 0; j < 4; j++) {
                uint32_t bfr[4];
                ldm_x4(bfr, sptr(&Vl[cp * 16 + vrow][j * 16 + vcol]));
                mma16816(O[2 * cp],     PA[j], bfr);
                mma16816(O[2 * cp + 1], PA[j], bfr + 2);
            }
        }
    }

    float il0 = 1.f / l0, il1 = 1.f / l1;
    int row = i0 + warp * 16 + (lane >> 2);
    int c2 = (lane & 3) * 2;
#pragma unroll
    for (int t = 0; t < 16; t++) {
        int c = t * 8 + c2;
        g_o[off + (size_t)c * NN + row]           = __float2half(O[t][0] * il0);
        g_o[off + (size_t)(c + 1) * NN + row]     = __float2half(O[t][1] * il0);
        g_o[off + (size_t)c * NN + row + 8]       = __float2half(O[t][2] * il1);
        g_o[off + (size_t)(c + 1) * NN + row + 8] = __float2half(O[t][3] * il1);
    }
}

// ---------------- kernel 4: final projection + bias + residual ----------------
__global__ __launch_bounds__(256, 2) void proj_kernel(
    const float* __restrict__ x, const float* __restrict__ wf,
    const float* __restrict__ bf, float* __restrict__ out)
{
    __shared__ __half os[128][136];
    int b = blockIdx.y, p0 = blockIdx.x * 128;
    int tid = threadIdx.x;
    size_t off = (size_t)b * NC * NN;
    const __half* op = g_o + off + p0;
    for (int idx = tid; idx < 2048; idx += 256) {
        int c = idx >> 4, u = idx & 15;
        *(uint4*)&os[c][u * 8] = *(const uint4*)(op + (size_t)c * NN + u * 8);
    }
    __syncthreads();

    int warp = tid >> 5, lane = tid & 31;
    int oc0 = warp * 16, rr = lane >> 2, c2 = (lane & 3) * 2;
    int browoff = (lane & 7) + 8 * ((lane >> 3) & 1);
    int bcol = 8 * (lane >> 4);

    uint32_t A[8][4];
#pragma unroll
    for (int kb = 0; kb < 8; kb++) {
        int cc = kb * 16 + c2;
        float2 x0 = *(const float2*)(wf + (size_t)(oc0 + rr) * NC + cc);
        float2 x1 = *(const float2*)(wf + (size_t)(oc0 + rr + 8) * NC + cc);
        float2 x2 = *(const float2*)(wf + (size_t)(oc0 + rr) * NC + cc + 8);
        float2 x3 = *(const float2*)(wf + (size_t)(oc0 + rr + 8) * NC + cc + 8);
        A[kb][0] = packh2(x0.x, x0.y); A[kb][1] = packh2(x1.x, x1.y);
        A[kb][2] = packh2(x2.x, x2.y); A[kb][3] = packh2(x3.x, x3.y);
    }
    float br = bf[oc0 + rr], br8 = bf[oc0 + rr + 8];
    const float* xb = x + off;
    float* ob = out + off;

#pragma unroll
    for (int pp = 0; pp < 8; pp++) {
        float acc[8] = {0.f, 0.f, 0.f, 0.f, 0.f, 0.f, 0.f, 0.f};
#pragma unroll
        for (int kb = 0; kb < 8; kb++) {
            uint32_t bfr[4];
            ldm_x4_t(bfr, sptr(&os[kb * 16 + browoff][pp * 16 + bcol]));
            mma16816(acc,     A[kb], bfr);
            mma16816(acc + 4, A[kb], bfr + 2);
        }
        int pc = p0 + pp * 16 + c2;
        size_t i00 = (size_t)(oc0 + rr) * NN + pc;
        size_t i10 = (size_t)(oc0 + rr + 8) * NN + pc;
        float2 xv;
        xv = *(const float2*)(xb + i00);
        *(float2*)(ob + i00) = make_float2(acc[0] + br + xv.x, acc[1] + br + xv.y);
        xv = *(const float2*)(xb + i10);
        *(float2*)(ob + i10) = make_float2(acc[2] + br8 + xv.x, acc[3] + br8 + xv.y);
        xv = *(const float2*)(xb + i00 + 8);
        *(float2*)(ob + i00 + 8) = make_float2(acc[4] + br + xv.x, acc[5] + br + xv.y);
        xv = *(const float2*)(xb + i10 + 8);
        *(float2*)(ob + i10 + 8) = make_float2(acc[6] + br8 + xv.x, acc[7] + br8 + xv.y);
    }
}

// ---------------- launch ----------------
extern "C" void kernel_launch(void* const* d_in, const int* in_sizes, int n_in,
                              void* d_out, int out_size)
{
    (void)in_sizes; (void)n_in; (void)out_size;
    const float* x  = (const float*)d_in[0];
    const float* gw = (const float*)d_in[1];
    const float* gb = (const float*)d_in[2];
    const float* wq = (const float*)d_in[3];
    const float* bq = (const float*)d_in[4];
    const float* wk = (const float*)d_in[5];
    const float* bk = (const float*)d_in[6];
    const float* wv = (const float*)d_in[7];
    const float* bv = (const float*)d_in[8];
    const float* wf = (const float*)d_in[9];
    const float* bf = (const float*)d_in[10];
    float* out = (float*)d_out;

    static_assert(ATTN_SMEM == 110592, "smem size");
    cudaFuncSetAttribute(attn_kernel, cudaFuncAttributeMaxDynamicSharedMemorySize, ATTN_SMEM);

    gn_stats_kernel<<<NB * NGROUPS, 256>>>(x);
    qkv_kernel<<<dim3(32, NB), 256>>>(x, gw, gb, wq, bq, wk, bk, wv, bv);
    attn_kernel<<<dim3(32, NB), 256, ATTN_SMEM>>>();
    proj_kernel<<<dim3(32, NB), 256>>>(x, wf, bf, out);
}

// round 11
// speedup vs baseline: 1.6791x; 1.0913x over previous
#include <cuda_runtime.h>
#include <cuda_fp16.h>
#include <cstdint>

#define NB 16
#define NC 128
#define NN 4096
#define NGROUPS 8
#define CPG 16
#define LOG2E 1.4426950408889634f

// ---------------- scratch ----------------
__device__ float  g_mean[NB * NGROUPS];
__device__ float  g_rstd[NB * NGROUPS];
__device__ __half g_q[(size_t)NB * NC * NN];
__device__ __half g_k[(size_t)NB * NC * NN];
__device__ __half g_v[(size_t)NB * NC * NN];

// ---------------- helpers ----------------
__device__ __forceinline__ uint32_t sptr(const void* p) {
    return (uint32_t)__cvta_generic_to_shared(p);
}
__device__ __forceinline__ void ldm_x4(uint32_t* r, uint32_t a) {
    asm volatile("ldmatrix.sync.aligned.m8n8.x4.shared.b16 {%0,%1,%2,%3}, [%4];"
                 : "=r"(r[0]), "=r"(r[1]), "=r"(r[2]), "=r"(r[3]) : "r"(a));
}
__device__ __forceinline__ void ldm_x4_t(uint32_t* r, uint32_t a) {
    asm volatile("ldmatrix.sync.aligned.m8n8.x4.trans.shared.b16 {%0,%1,%2,%3}, [%4];"
                 : "=r"(r[0]), "=r"(r[1]), "=r"(r[2]), "=r"(r[3]) : "r"(a));
}
__device__ __forceinline__ void mma16816(float* c, const uint32_t* a, const uint32_t* b) {
    asm volatile("mma.sync.aligned.m16n8k16.row.col.f32.f16.f16.f32 "
                 "{%0,%1,%2,%3}, {%4,%5,%6,%7}, {%8,%9}, {%0,%1,%2,%3};"
                 : "+f"(c[0]), "+f"(c[1]), "+f"(c[2]), "+f"(c[3])
                 : "r"(a[0]), "r"(a[1]), "r"(a[2]), "r"(a[3]), "r"(b[0]), "r"(b[1]));
}
__device__ __forceinline__ float ex2f(float x) {
    float y; asm("ex2.approx.f32 %0, %1;" : "=f"(y) : "f"(x)); return y;
}
__device__ __forceinline__ uint32_t exp2pack(float lo, float hi) {
    uint32_t h, r;
    asm("cvt.rn.f16x2.f32 %0, %1, %2;" : "=r"(h) : "f"(hi), "f"(lo));
    asm("ex2.approx.f16x2 %0, %1;" : "=r"(r) : "r"(h));
    return r;
}
__device__ __forceinline__ uint32_t packh2(float a, float b) {
    __half2 h = __floats2half2_rn(a, b);
    return *reinterpret_cast<uint32_t*>(&h);
}
__device__ __forceinline__ void cpa16(void* dst, const void* src) {
    asm volatile("cp.async.cg.shared.global [%0], [%1], 16;\n"
                 :: "r"(sptr(dst)), "l"(src));
}
#define CP_COMMIT() asm volatile("cp.async.commit_group;")

// ---------------- kernel 1: groupnorm stats ----------------
__global__ void gn_stats_kernel(const float* __restrict__ x) {
    int bg = blockIdx.x;
    const float* xp = x + (size_t)bg * (CPG * NN);
    float s = 0.f, ss = 0.f;
    for (int i = threadIdx.x * 4; i < CPG * NN; i += 256 * 4) {
        float4 v = *(const float4*)(xp + i);
        s  += (v.x + v.y) + (v.z + v.w);
        ss += v.x * v.x + v.y * v.y + v.z * v.z + v.w * v.w;
    }
#pragma unroll
    for (int o = 16; o; o >>= 1) {
        s  += __shfl_xor_sync(~0u, s, o);
        ss += __shfl_xor_sync(~0u, ss, o);
    }
    __shared__ float red[16];
    int warp = threadIdx.x >> 5;
    if ((threadIdx.x & 31) == 0) { red[warp] = s; red[8 + warp] = ss; }
    __syncthreads();
    if (threadIdx.x == 0) {
        float S = 0.f, SS = 0.f;
        for (int i = 0; i < 8; i++) { S += red[i]; SS += red[8 + i]; }
        float inv = 1.f / (float)(CPG * NN);
        float mean = S * inv;
        float var  = SS * inv - mean * mean;
        g_mean[bg] = mean;
        g_rstd[bg] = rsqrtf(var + 1e-5f);
    }
}

// ---------------- kernel 2: GN apply + QKV projection (fp16 mma) ----------------
__global__ __launch_bounds__(256, 1) void qkv_kernel(
    const float* __restrict__ x, const float* __restrict__ gnw, const float* __restrict__ gnb,
    const float* __restrict__ wq, const float* __restrict__ bq,
    const float* __restrict__ wk, const float* __restrict__ bk,
    const float* __restrict__ wv, const float* __restrict__ bv)
{
    __shared__ __half xs[128][136];
    int b = blockIdx.y, p0 = blockIdx.x * 128;
    int tid = threadIdx.x;
    const float* xb = x + (size_t)b * NC * NN;

    for (int idx = tid; idx < 128 * 32; idx += 256) {
        int c = idx >> 5, u = idx & 31;
        float4 v = *(const float4*)(xb + (size_t)c * NN + p0 + u * 4);
        float rstd = g_rstd[b * NGROUPS + (c >> 4)];
        float mean = g_mean[b * NGROUPS + (c >> 4)];
        float ga = gnw[c] * rstd;
        float be = gnb[c] - mean * ga;
        __half2* d = (__half2*)&xs[c][u * 4];
        d[0] = __floats2half2_rn(v.x * ga + be, v.y * ga + be);
        d[1] = __floats2half2_rn(v.z * ga + be, v.w * ga + be);
    }
    __syncthreads();

    int warp = tid >> 5, lane = tid & 31;
    int oc0 = warp * 16;
    int rr = lane >> 2, c2 = (lane & 3) * 2;
    int browoff = (lane & 7) + 8 * ((lane >> 3) & 1);
    int bcol = 8 * (lane >> 4);

    const float* Ws[3] = {wq, wk, wv};
    const float* Bi[3] = {bq, bk, bv};
    __half* Out[3] = {g_q + (size_t)b * NC * NN, g_k + (size_t)b * NC * NN, g_v + (size_t)b * NC * NN};
    const float qscale = 0.08838834764831845f * LOG2E;

    for (int m = 0; m < 3; m++) {
        const float* W = Ws[m];
        uint32_t A[8][4];
#pragma unroll
        for (int kb = 0; kb < 8; kb++) {
            int cc = kb * 16 + c2;
            float2 x0 = *(const float2*)(W + (size_t)(oc0 + rr) * NC + cc);
            float2 x1 = *(const float2*)(W + (size_t)(oc0 + rr + 8) * NC + cc);
            float2 x2 = *(const float2*)(W + (size_t)(oc0 + rr) * NC + cc + 8);
            float2 x3 = *(const float2*)(W + (size_t)(oc0 + rr + 8) * NC + cc + 8);
            A[kb][0] = packh2(x0.x, x0.y); A[kb][1] = packh2(x1.x, x1.y);
            A[kb][2] = packh2(x2.x, x2.y); A[kb][3] = packh2(x3.x, x3.y);
        }
        float br  = Bi[m][oc0 + rr];
        float br8 = Bi[m][oc0 + rr + 8];
        float sc = (m == 0) ? qscale : 1.f;
        __half* out = Out[m];
#pragma unroll
        for (int pp = 0; pp < 8; pp++) {
            float acc[8] = {0.f, 0.f, 0.f, 0.f, 0.f, 0.f, 0.f, 0.f};
#pragma unroll
            for (int kb = 0; kb < 8; kb++) {
                uint32_t bfr[4];
                ldm_x4_t(bfr, sptr(&xs[kb * 16 + browoff][pp * 16 + bcol]));
                mma16816(acc,     A[kb], bfr);
                mma16816(acc + 4, A[kb], bfr + 2);
            }
            int pc = p0 + pp * 16 + c2;
            *(__half2*)(out + (size_t)(oc0 + rr) * NN + pc)         = __floats2half2_rn((acc[0] + br) * sc, (acc[1] + br) * sc);
            *(__half2*)(out + (size_t)(oc0 + rr + 8) * NN + pc)     = __floats2half2_rn((acc[2] + br8) * sc, (acc[3] + br8) * sc);
            *(__half2*)(out + (size_t)(oc0 + rr) * NN + pc + 8)     = __floats2half2_rn((acc[4] + br) * sc, (acc[5] + br) * sc);
            *(__half2*)(out + (size_t)(oc0 + rr + 8) * NN + pc + 8) = __floats2half2_rn((acc[6] + br8) * sc, (acc[7] + br8) * sc);
        }
    }
}

// ---------------- kernel 3: flash attention + fused output projection ----------------
#define STAGE_H (2 * 128 * 72)               // halves per stage
#define ATTN_SMEM (3 * STAGE_H * 2)          // 110592 bytes

__global__ __launch_bounds__(256, 1) void attn_kernel(
    const float* __restrict__ x, const float* __restrict__ wf,
    const float* __restrict__ bf, float* __restrict__ out)
{
    extern __shared__ __half dyn[];
    __shared__ float bfs[128];

    int b = blockIdx.y, i0 = blockIdx.x * 128;
    int tid = threadIdx.x, warp = tid >> 5, lane = tid & 31;
    size_t off = (size_t)b * NC * NN;

    // ---- stage Q tile; build A-frags ----
    {
        __half (*Qs)[136] = (__half(*)[136])dyn;
        const __half* qp = g_q + off + i0;
        for (int idx = tid; idx < 2048; idx += 256) {
            int d = idx >> 4, u = idx & 15;
            *(uint4*)&Qs[d][u * 8] = *(const uint4*)(qp + (size_t)d * NN + u * 8);
        }
    }
    __syncthreads();
    uint32_t QA[8][4];
    {
        __half (*Qs)[136] = (__half(*)[136])dyn;
        int r  = 8 * (lane >> 4) + (lane & 7);
        int cq = warp * 16 + 8 * ((lane >> 3) & 1);
#pragma unroll
        for (int kb = 0; kb < 8; kb++)
            ldm_x4_t(QA[kb], sptr(&Qs[kb * 16 + r][cq]));
    }
    __syncthreads();

    // ---- prologue: prefetch stages 0,1,2 ----
    {
        const __half* kb0 = g_k + off;
        const __half* vb0 = g_v + off;
#pragma unroll
        for (int s = 0; s < 3; s++) {
            __half* ks = dyn + s * STAGE_H;
            __half* vs = ks + 128 * 72;
            const __half* kp = kb0 + s * 64;
            const __half* vp = vb0 + s * 64;
#pragma unroll
            for (int it = 0; it < 4; it++) {
                int i = tid + it * 256;
                int c = i >> 3, u = i & 7;
                cpa16(ks + c * 72 + u * 8, kp + (size_t)c * NN + u * 8);
                cpa16(vs + c * 72 + u * 8, vp + (size_t)c * NN + u * 8);
            }
            CP_COMMIT();
        }
    }

    float O[16][4];
#pragma unroll
    for (int i = 0; i < 16; i++) { O[i][0] = O[i][1] = O[i][2] = O[i][3] = 0.f; }
    float m0 = -1e30f, m1 = -1e30f, l0 = 0.f, l1 = 0.f;

    int krow = (lane & 7) + 8 * ((lane >> 3) & 1);
    int kcol = 8 * (lane >> 4);
    int vrow = 8 * (lane >> 4) + (lane & 7);
    int vcol = 8 * ((lane >> 3) & 1);

    for (int jb = 0; jb < 64; jb++) {
        if (jb <= 61)      asm volatile("cp.async.wait_group 2;");
        else if (jb == 62) asm volatile("cp.async.wait_group 1;");
        else               asm volatile("cp.async.wait_group 0;");
        __syncthreads();

        int st = jb % 3;
        __half (*Ks)[72] = (__half(*)[72])(dyn + st * STAGE_H);
        __half (*Vs)[72] = (__half(*)[72])(dyn + st * STAGE_H + 128 * 72);

        // S = Q K^T (log2-scaled already)
        float S[8][4];
#pragma unroll
        for (int jp = 0; jp < 4; jp++) {
            float* s0 = S[2 * jp];
            float* s1 = S[2 * jp + 1];
            s0[0] = s0[1] = s0[2] = s0[3] = 0.f;
            s1[0] = s1[1] = s1[2] = s1[3] = 0.f;
#pragma unroll
            for (int kb = 0; kb < 8; kb++) {
                uint32_t bfr[4];
                ldm_x4_t(bfr, sptr(&Ks[kb * 16 + krow][jp * 16 + kcol]));
                mma16816(s0, QA[kb], bfr);
                mma16816(s1, QA[kb], bfr + 2);
            }
        }

        // online softmax (f16x2 exp; results ARE the PV A-frags)
        float r0 = S[0][0], r1 = S[0][2];
#pragma unroll
        for (int t = 0; t < 8; t++) {
            r0 = fmaxf(r0, fmaxf(S[t][0], S[t][1]));
            r1 = fmaxf(r1, fmaxf(S[t][2], S[t][3]));
        }
        r0 = fmaxf(r0, __shfl_xor_sync(~0u, r0, 1)); r0 = fmaxf(r0, __shfl_xor_sync(~0u, r0, 2));
        r1 = fmaxf(r1, __shfl_xor_sync(~0u, r1, 1)); r1 = fmaxf(r1, __shfl_xor_sync(~0u, r1, 2));
        float nm0 = fmaxf(m0, r0), nm1 = fmaxf(m1, r1);
        float a0 = ex2f(m0 - nm0), a1 = ex2f(m1 - nm1);
        m0 = nm0; m1 = nm1;

        uint32_t PA[4][4];
        __half2 hs0 = __floats2half2_rn(0.f, 0.f), hs1 = hs0;
#pragma unroll
        for (int j = 0; j < 4; j++) {
            PA[j][0] = exp2pack(S[2*j][0]   - nm0, S[2*j][1]   - nm0);
            PA[j][1] = exp2pack(S[2*j][2]   - nm1, S[2*j][3]   - nm1);
            PA[j][2] = exp2pack(S[2*j+1][0] - nm0, S[2*j+1][1] - nm0);
            PA[j][3] = exp2pack(S[2*j+1][2] - nm1, S[2*j+1][3] - nm1);
            hs0 = __hadd2(hs0, __hadd2(*(__half2*)&PA[j][0], *(__half2*)&PA[j][2]));
            hs1 = __hadd2(hs1, __hadd2(*(__half2*)&PA[j][1], *(__half2*)&PA[j][3]));
        }
        float rs0 = __low2float(hs0) + __high2float(hs0);
        float rs1 = __low2float(hs1) + __high2float(hs1);
        rs0 += __shfl_xor_sync(~0u, rs0, 1); rs0 += __shfl_xor_sync(~0u, rs0, 2);
        rs1 += __shfl_xor_sync(~0u, rs1, 1); rs1 += __shfl_xor_sync(~0u, rs1, 2);
        l0 = l0 * a0 + rs0;
        l1 = l1 * a1 + rs1;
#pragma unroll
        for (int t = 0; t < 16; t++) { O[t][0] *= a0; O[t][1] *= a0; O[t][2] *= a1; O[t][3] *= a1; }

        // O += P V
#pragma unroll
        for (int cp = 0; cp < 8; cp++) {
#pragma unroll
            for (int j = 0; j < 4; j++) {
                uint32_t bfr[4];
                ldm_x4(bfr, sptr(&Vs[cp * 16 + vrow][j * 16 + vcol]));
                mma16816(O[2 * cp],     PA[j], bfr);
                mma16816(O[2 * cp + 1], PA[j], bfr + 2);
            }
        }
        __syncthreads();

        if (jb + 3 < 64) {
            __half* ks = dyn + st * STAGE_H;
            __half* vs = ks + 128 * 72;
            const __half* kp = g_k + off + (jb + 3) * 64;
            const __half* vp = g_v + off + (jb + 3) * 64;
#pragma unroll
            for (int it = 0; it < 4; it++) {
                int i = tid + it * 256;
                int c = i >> 3, u = i & 7;
                cpa16(ks + c * 72 + u * 8, kp + (size_t)c * NN + u * 8);
                cpa16(vs + c * 72 + u * 8, vp + (size_t)c * NN + u * 8);
            }
        }
        CP_COMMIT();
    }

    // ================= fused output projection epilogue =================
    // stage wf [oc][c] f16 into smem (reuse K/V buffer) + bias
    __syncthreads();
    {
        __half (*wfs)[136] = (__half(*)[136])dyn;
        for (int idx = tid; idx < 128 * 32; idx += 256) {
            int oc = idx >> 5, u = idx & 31;
            float4 v = *(const float4*)(wf + (size_t)oc * NC + u * 4);
            __half2* d = (__half2*)&wfs[oc][u * 4];
            d[0] = __floats2half2_rn(v.x, v.y);
            d[1] = __floats2half2_rn(v.z, v.w);
        }
        if (tid < 128) bfs[tid] = bf[tid];
    }

    // pack normalized o into A-frags (rows = position, k = channel)
    float il0 = 1.f / l0, il1 = 1.f / l1;
    uint32_t AN[8][4];
#pragma unroll
    for (int kb = 0; kb < 8; kb++) {
        AN[kb][0] = packh2(O[2*kb][0]   * il0, O[2*kb][1]   * il0);
        AN[kb][1] = packh2(O[2*kb][2]   * il1, O[2*kb][3]   * il1);
        AN[kb][2] = packh2(O[2*kb+1][0] * il0, O[2*kb+1][1] * il0);
        AN[kb][3] = packh2(O[2*kb+1][2] * il1, O[2*kb+1][3] * il1);
    }
    __syncthreads();

    // R[pos][oc] = o_norm x wf^T  (B-frags from wfs[oc][c], V-fragment pattern)
    {
        __half (*wfs)[136] = (__half(*)[136])dyn;
        float R[16][4];
#pragma unroll
        for (int i = 0; i < 16; i++) { R[i][0] = R[i][1] = R[i][2] = R[i][3] = 0.f; }
#pragma unroll
        for (int ob = 0; ob < 8; ob++) {
#pragma unroll
            for (int kb = 0; kb < 8; kb++) {
                uint32_t bfr[4];
                ldm_x4(bfr, sptr(&wfs[ob * 16 + vrow][kb * 16 + vcol]));
                mma16816(R[2 * ob],     AN[kb], bfr);
                mma16816(R[2 * ob + 1], AN[kb], bfr + 2);
            }
        }

        // out[oc][pos] = R + bias + x (residual)
        int row = i0 + warp * 16 + (lane >> 2);
        int c2 = (lane & 3) * 2;
        const float* xb = x + off;
        float* ob2 = out + off;
#pragma unroll
        for (int t = 0; t < 16; t++) {
            int oc = t * 8 + c2;
            size_t a0i = (size_t)oc * NN + row;
            size_t a1i = (size_t)(oc + 1) * NN + row;
            float b0 = bfs[oc], b1 = bfs[oc + 1];
            ob2[a0i]     = R[t][0] + b0 + xb[a0i];
            ob2[a1i]     = R[t][1] + b1 + xb[a1i];
            ob2[a0i + 8] = R[t][2] + b0 + xb[a0i + 8];
            ob2[a1i + 8] = R[t][3] + b1 + xb[a1i + 8];
        }
    }
}

// ---------------- launch ----------------
extern "C" void kernel_launch(void* const* d_in, const int* in_sizes, int n_in,
                              void* d_out, int out_size)
{
    (void)in_sizes; (void)n_in; (void)out_size;
    const float* x  = (const float*)d_in[0];
    const float* gw = (const float*)d_in[1];
    const float* gb = (const float*)d_in[2];
    const float* wq = (const float*)d_in[3];
    const float* bq = (const float*)d_in[4];
    const float* wk = (const float*)d_in[5];
    const float* bk = (const float*)d_in[6];
    const float* wv = (const float*)d_in[7];
    const float* bv = (const float*)d_in[8];
    const float* wf = (const float*)d_in[9];
    const float* bf = (const float*)d_in[10];
    float* out = (float*)d_out;

    static_assert(ATTN_SMEM == 110592, "smem size");
    cudaFuncSetAttribute(attn_kernel, cudaFuncAttributeMaxDynamicSharedMemorySize, ATTN_SMEM);

    gn_stats_kernel<<<NB * NGROUPS, 256>>>(x);
    qkv_kernel<<<dim3(32, NB), 256>>>(x, gw, gb, wq, bq, wk, bk, wv, bv);
    attn_kernel<<<dim3(32, NB), 256, ATTN_SMEM>>>(x, wf, bf, out);
}